// round 14
// baseline (speedup 1.0000x reference)
#include <cuda_runtime.h>
#include <cuda_fp16.h>

#define W_  640
#define H_  480
#define HW  307200
#define CS  12
#define CI  16
#define CT  28
#define CP  14    // channel pairs (sem pairs 0..5, ins pairs 6..13)

// ex2.approx.f16x2: one MUFU op, two exps (base 2)
__device__ __forceinline__ __half2 h2ex2(__half2 a) {
    __half2 d;
    asm("ex2.approx.f16x2 %0, %1;"
        : "=r"(*(unsigned*)&d) : "r"(*(unsigned*)&a));
    return d;
}

// ---------------- scratch (device globals, no allocation) ----------------
// Weight pair planes: o2=0..11 hold offsets (2*o2 + (o2>=6), +1); plane 12 = center (.x)
__device__ __half2 g_w2[13 * HW];
__device__ __half2 g_qa[CP * HW];    // q buffer A, channel-pair packed
__device__ __half2 g_qb[CP * HW];    // q buffer B
__device__ __half2 g_blur2[CP * HW]; // blur output, channel-pair packed
__device__ __half2 g_lg2[CP * HW];   // logits, channel-pair packed fp16

// 13-tap Gaussian sigma=3 as fp16x2 bit patterns (k,k)
__constant__ unsigned c_gkh2[13] = {
    0x24BF24BFu, 0x28602860u, 0x2B362B36u, 0x2D522D52u, 0x2F062F06u,
    0x30263026u, 0x30623062u, 0x30263026u, 0x2F062F06u, 0x2D522D52u,
    0x2B362B36u, 0x28602860u, 0x24BF24BFu};

// -sd_o * (1/18) * log2(e), o = dy*5+dx
__constant__ float c_sdl[25] = {
    -0.6411978f, -0.4007486f, -0.3205989f, -0.4007486f, -0.6411978f,
    -0.4007486f, -0.1602994f, -0.0801497f, -0.1602994f, -0.4007486f,
    -0.3205989f, -0.0801497f,  0.0f,       -0.0801497f, -0.3205989f,
    -0.4007486f, -0.1602994f, -0.0801497f, -0.1602994f, -0.4007486f,
    -0.6411978f, -0.4007486f, -0.3205989f, -0.4007486f, -0.6411978f};

#define KC   (-32.0598869f)             // -(1/(2*0.15^2)) * log2(e)
#define L2E  (1.4426950408889634f)

// select weight for raw offset o (0..24) from the pair-packed register array
__device__ __forceinline__ __half wsel(const __half2* w, int o) {
    if (o < 12)  return (o & 1) ? __high2half(w[o >> 1]) : __low2half(w[o >> 1]);
    if (o == 12) return __low2half(w[12]);
    return ((o - 1) & 1) ? __high2half(w[(o - 1) >> 1]) : __low2half(w[(o - 1) >> 1]);
}

// ---------------- init: weights + initial softmax + logit packing ------------
__global__ void __launch_bounds__(256) kInit(const float* __restrict__ img,
                                             const float* __restrict__ slog,
                                             const float* __restrict__ ilog)
{
    __shared__ float simg[3][8][68];

    int tid = threadIdx.x;
    int x0 = blockIdx.x * 64;
    int y0 = blockIdx.y * 4;

    for (int idx = tid; idx < 8 * 68; idx += 256) {
        int r  = idx / 68;
        int cc = idx - r * 68;
        int gy = min(max(y0 + r - 2, 0), H_ - 1);
        int gx = min(max(x0 + cc - 2, 0), W_ - 1);
        int gp = gy * W_ + gx;
        simg[0][r][cc] = __ldg(img + gp);
        simg[1][r][cc] = __ldg(img + HW + gp);
        simg[2][r][cc] = __ldg(img + 2 * HW + gp);
    }
    __syncthreads();

    int tx = tid & 63, ty = tid >> 6;
    int p  = (y0 + ty) * W_ + x0 + tx;

    float r0 = simg[0][ty + 2][tx + 2];
    float g0 = simg[1][ty + 2][tx + 2];
    float b0 = simg[2][ty + 2][tx + 2];

    // 24 non-center weights as 12 f16x2 exps; center weight = 1 exactly
    float2 ef[12];
    float den = 1.0f;
    #pragma unroll
    for (int o2 = 0; o2 < 12; o2++) {
        int offA = 2 * o2 + (o2 >= 6 ? 1 : 0);
        int offB = offA + 1;
        float arg[2];
        #pragma unroll
        for (int k = 0; k < 2; k++) {
            int o  = k ? offB : offA;
            int dy = o / 5, dx = o % 5;
            float dr = r0 - simg[0][ty + dy][tx + dx];
            float dg = g0 - simg[1][ty + dy][tx + dx];
            float db = b0 - simg[2][ty + dy][tx + dx];
            float cd = fmaf(db, db, fmaf(dg, dg, dr * dr));
            arg[k] = fmaf(cd, KC, c_sdl[o]);
        }
        __half2 e2 = h2ex2(__floats2half2_rn(arg[0], arg[1]));
        float2 f = __half22float2(e2);
        den += f.x + f.y;
        ef[o2] = f;
    }
    float inv = __fdividef(1.0f, den);
    #pragma unroll
    for (int o2 = 0; o2 < 12; o2++)
        g_w2[o2 * HW + p] = __floats2half2_rn(ef[o2].x * inv, ef[o2].y * inv);
    g_w2[12 * HW + p] = __floats2half2_rn(inv, 0.f);

    // initial softmaxes via f16x2 ex2 + fp16 logit packing
    {
        float t[CS];
        float m = -1e30f;
        #pragma unroll
        for (int c = 0; c < CS; c++) { t[c] = __ldg(slog + c * HW + p); m = fmaxf(m, t[c]); }
        float mL = m * L2E;
        float2 ef2[CS / 2];
        float s = 0.f;
        #pragma unroll
        for (int cp = 0; cp < CS / 2; cp++) {
            g_lg2[cp * HW + p] = __floats2half2_rn(t[2 * cp], t[2 * cp + 1]);
            float a0 = fmaf(t[2 * cp],     L2E, -mL);
            float a1 = fmaf(t[2 * cp + 1], L2E, -mL);
            float2 f = __half22float2(h2ex2(__floats2half2_rn(a0, a1)));
            s += f.x + f.y;
            ef2[cp] = f;
        }
        float is = __fdividef(1.0f, s);
        #pragma unroll
        for (int cp = 0; cp < CS / 2; cp++)
            g_qa[cp * HW + p] = __floats2half2_rn(ef2[cp].x * is, ef2[cp].y * is);
    }
    {
        float t[CI];
        float m = -1e30f;
        #pragma unroll
        for (int c = 0; c < CI; c++) { t[c] = __ldg(ilog + c * HW + p); m = fmaxf(m, t[c]); }
        float mL = m * L2E;
        float2 ef2[CI / 2];
        float s = 0.f;
        #pragma unroll
        for (int cp = 0; cp < CI / 2; cp++) {
            g_lg2[(CS / 2 + cp) * HW + p] = __floats2half2_rn(t[2 * cp], t[2 * cp + 1]);
            float a0 = fmaf(t[2 * cp],     L2E, -mL);
            float a1 = fmaf(t[2 * cp + 1], L2E, -mL);
            float2 f = __half22float2(h2ex2(__floats2half2_rn(a0, a1)));
            s += f.x + f.y;
            ef2[cp] = f;
        }
        float is = __fdividef(1.0f, s);
        #pragma unroll
        for (int cp = 0; cp < CI / 2; cp++)
            g_qa[(CS / 2 + cp) * HW + p] = __floats2half2_rn(ef2[cp].x * is, ef2[cp].y * is);
    }
}

// ---------------- fused separable blur, all-fp16 HFMA2 path ------------------
#define BTX 64
#define BTY 32
#define HR  (BTY + 12)   // 44

__global__ void __launch_bounds__(256) kBlur(int src)
{
    const __half2* q = src ? g_qb : g_qa;
    __shared__ __half2 sH[HR][BTX];

    int c  = blockIdx.z;                 // pair index
    int x0 = blockIdx.x * BTX;
    int y0 = blockIdx.y * BTY;
    const __half2* plane = q + c * HW;
    int tid = threadIdx.x;

    bool interior = (blockIdx.x >= 1 && blockIdx.x <= 8 &&
                     blockIdx.y >= 1 && blockIdx.y <= (H_ / BTY) - 2);

    // H stage: 44 rows x 8 groups of 8 outputs = 352 tasks
    for (int t = tid; t < HR * 8; t += 256) {
        int r = t >> 3;
        int g = t & 7;
        int gy = y0 + r - 6;
        int xb = x0 + g * 8 - 8;         // 4-elem (16B) aligned
        __half2 f16[24];
        if (interior) {
            #pragma unroll
            for (int s = 0; s < 6; s++) {
                float4 v = __ldg((const float4*)(plane + gy * W_ + xb) + s);
                *(float4*)&f16[s * 4] = v;
            }
        } else if (gy >= 0 && gy < H_) {
            const __half2* row = plane + gy * W_;
            #pragma unroll
            for (int s = 0; s < 6; s++) {
                int xs = xb + s * 4;
                if (xs >= 0 && xs + 3 < W_) {
                    float4 v = __ldg((const float4*)(row + xs));
                    *(float4*)&f16[s * 4] = v;
                } else {
                    #pragma unroll
                    for (int k = 0; k < 4; k++) {
                        int xx = xs + k;
                        f16[s * 4 + k] = (xx >= 0 && xx < W_) ? __ldg(row + xx)
                                                              : __float2half2_rn(0.f);
                    }
                }
            }
        } else {
            #pragma unroll
            for (int k = 0; k < 24; k++) f16[k] = __float2half2_rn(0.f);
        }
        #pragma unroll
        for (int j = 0; j < 8; j++) {
            __half2 a = __float2half2_rn(0.f);
            #pragma unroll
            for (int tt = 0; tt < 13; tt++)
                a = __hfma2(*(const __half2*)&c_gkh2[tt], f16[j + 2 + tt], a);
            sH[r][g * 8 + j] = a;
        }
    }
    __syncthreads();

    // V stage: each thread 8 consecutive rows, sliding window over 20 sH rows
    int tx = tid & 63, ty = tid >> 6;    // ty 0..3
    __half2 acc[8];
    #pragma unroll
    for (int k = 0; k < 8; k++) acc[k] = __float2half2_rn(0.f);
    #pragma unroll
    for (int t = 0; t < 20; t++) {
        __half2 v = sH[ty * 8 + t][tx];
        #pragma unroll
        for (int k = 0; k < 8; k++) {
            int tt = t - k;
            if (tt >= 0 && tt < 13)
                acc[k] = __hfma2(*(const __half2*)&c_gkh2[tt], v, acc[k]);
        }
    }
    #pragma unroll
    for (int k = 0; k < 8; k++)
        g_blur2[c * HW + (y0 + ty * 8 + k) * W_ + x0 + tx] = acc[k];
}

// ---------------- fused: bilateral (HFMA2, 2-row blocked) + compat + cross ---
#define FTX 64
#define FTY 8
#define TCOL 72
#define TROW 12
#define TSZ  (TCOL * TROW)   // 864 half2 per pair-plane

__global__ void __launch_bounds__(256, 2) kFused(
    int src, float* __restrict__ dout,
    const int*   __restrict__ labels,
    const float* __restrict__ ssw_g, const float* __restrict__ sbw_g,
    const float* __restrict__ compat_g,
    const float* __restrict__ isw_g, const float* __restrict__ ibw_g,
    const float* __restrict__ cis_g, const float* __restrict__ csi_g)
{
    extern __shared__ float sm[];
    __half2* sqh     = (__half2*)sm;              // CP * TSZ half2
    float* s_compat  = sm + CP * TSZ;             // 144
    float* s_mis     = s_compat + 144;            // 192
    float* s_csi     = s_mis + 192;               // 192
    float* s_sw      = s_csi + 192;               // 16
    float* s_bw      = s_sw + 16;                 // 16
    float* s_ssw     = s_bw + 16;                 // 12
    float* s_sbw     = s_ssw + 12;                // 12

    const __half2* q = src ? g_qb : g_qa;
    __half2* qn2 = src ? g_qa : g_qb;

    int tid = threadIdx.x;

    if (tid < CS * CS) s_compat[tid] = compat_g[tid];
    if (tid >= 160 && tid < 160 + CI) {
        int j = tid - 160;
        int l = labels[j];
        s_sw[j] = isw_g[l];
        s_bw[j] = ibw_g[l];
        #pragma unroll
        for (int s = 0; s < CS; s++) {
            s_mis[j * CS + s] = cis_g[l * CS + s];
            s_csi[j * CS + s] = csi_g[l * CS + s];
        }
    }
    if (tid >= 192 && tid < 192 + CS) {
        int s = tid - 192;
        s_ssw[s] = ssw_g[s];
        s_sbw[s] = sbw_g[s];
    }

    int x0 = blockIdx.x * FTX;
    int y0 = blockIdx.y * FTY;

    // fill q tile (half2 pairs) for all 14 pair-planes
    if (blockIdx.x >= 1 && blockIdx.x <= 8) {
        // 12 rows x 18 float4 groups = 216 tasks
        if (tid < TROW * (TCOL / 4)) {
            int r  = tid / (TCOL / 4);
            int c4 = tid - r * (TCOL / 4);
            int gy = min(max(y0 + r - 2, 0), H_ - 1);
            #pragma unroll
            for (int cp = 0; cp < CP; cp++) {
                float4 v = __ldg((const float4*)(q + cp * HW + gy * W_ + x0 - 4) + c4);
                *(float4*)(sqh + cp * TSZ + r * TCOL + c4 * 4) = v;
            }
        }
    } else {
        for (int idx = tid; idx < TROW * TCOL; idx += 256) {
            int r  = idx / TCOL;
            int cc = idx - r * TCOL;
            int gy = min(max(y0 + r - 2, 0), H_ - 1);
            int gx = min(max(x0 + cc - 4, 0), W_ - 1);
            #pragma unroll
            for (int cp = 0; cp < CP; cp++)
                sqh[cp * TSZ + r * TCOL + cc] = __ldg(q + cp * HW + gy * W_ + gx);
        }
    }
    __syncthreads();

    int tx = tid & 63;
    int r0 = (tid >> 6) * 2;             // this thread's two output rows: r0, r0+1
    int p0 = (y0 + r0) * W_ + x0 + tx;
    int p1 = p0 + W_;

    // per-pixel weights for both rows
    __half2 wph0[13], wph1[13];
    #pragma unroll
    for (int o2 = 0; o2 < 13; o2++) {
        wph0[o2] = __ldg(&g_w2[o2 * HW + p0]);
        wph1[o2] = __ldg(&g_w2[o2 * HW + p1]);
    }

    // ---- bilateral: shared 6x5 window serves both rows; 420 LDS, 700 HFMA2 --
    __half2 acc0[CP], acc1[CP];
    #pragma unroll
    for (int cp = 0; cp < CP; cp++) {
        acc0[cp] = __float2half2_rn(0.f);
        acc1[cp] = __float2half2_rn(0.f);
    }

    #pragma unroll
    for (int k = 0; k < 6; k++) {
        #pragma unroll
        for (int dx = 0; dx < 5; dx++) {
            const __half2* base = sqh + (r0 + k) * TCOL + (tx + dx + 2);
            __half2 w0b = __float2half2_rn(0.f), w1b = __float2half2_rn(0.f);
            if (k < 5)  w0b = __half2half2(wsel(wph0, k * 5 + dx));
            if (k >= 1) w1b = __half2half2(wsel(wph1, (k - 1) * 5 + dx));
            #pragma unroll
            for (int cp = 0; cp < CP; cp++) {
                __half2 v = base[cp * TSZ];
                if (k < 5)  acc0[cp] = __hfma2(w0b, v, acc0[cp]);
                if (k >= 1) acc1[cp] = __hfma2(w1b, v, acc1[cp]);
            }
        }
    }

    // ---- per-pixel epilogue, fully unrolled over the two rows ----
    #pragma unroll
    for (int px = 0; px < 2; px++) {
        int p = px ? p1 : p0;

        float bil[CT];
        #pragma unroll
        for (int cp = 0; cp < CP; cp++) {
            float2 f = __half22float2(px ? acc1[cp] : acc0[cp]);
            bil[2 * cp]     = f.x;
            bil[2 * cp + 1] = f.y;
        }

        float blv[CT];
        #pragma unroll
        for (int cp = 0; cp < CP; cp++) {
            float2 b = __half22float2(__ldg(&g_blur2[cp * HW + p]));
            blv[2 * cp]     = b.x;
            blv[2 * cp + 1] = b.y;
        }

        float contrib[CS];
        #pragma unroll
        for (int s = 0; s < CS; s++)
            contrib[s] = s_ssw[s] * blv[s] + s_sbw[s] * bil[s];

        // tmp_sem: lazy per-pair fp16 logit loads (short live ranges — no hoisting)
        float tmp_sem[CS];
        #pragma unroll
        for (int cp2 = 0; cp2 < CS / 2; cp2++) {
            float2 l = __half22float2(__ldg(&g_lg2[cp2 * HW + p]));
            #pragma unroll
            for (int k = 0; k < 2; k++) {
                int o2 = 2 * cp2 + k;
                float acc = k ? l.y : l.x;
                #pragma unroll
                for (int i = 0; i < CS; i++)
                    acc = fmaf(s_compat[i * CS + o2], contrib[i], acc);
                tmp_sem[o2] = acc;
            }
        }

        // tmp_ins: lazy per-pair fp16 logit loads
        float tmp_ins[CI];
        #pragma unroll
        for (int cp2 = 0; cp2 < CI / 2; cp2++) {
            float2 l = __half22float2(__ldg(&g_lg2[(CS / 2 + cp2) * HW + p]));
            int j0 = 2 * cp2, j1 = 2 * cp2 + 1;
            tmp_ins[j0] = l.x + s_sw[j0] * blv[CS + j0] + s_bw[j0] * bil[CS + j0];
            tmp_ins[j1] = l.y + s_sw[j1] * blv[CS + j1] + s_bw[j1] * bil[CS + j1];
        }

        float e_ins[CI];
        {
            float m = -1e30f;
            #pragma unroll
            for (int j = 0; j < CI; j++) m = fmaxf(m, tmp_ins[j]);
            float s = 0.f;
            #pragma unroll
            for (int j = 0; j < CI; j++) { e_ins[j] = __expf(tmp_ins[j] - m); s += e_ins[j]; }
            float is = 1.0f / s;
            #pragma unroll
            for (int j = 0; j < CI; j++) e_ins[j] *= is;
        }
        float e_sem[CS];
        {
            float m = -1e30f;
            #pragma unroll
            for (int i = 0; i < CS; i++) m = fmaxf(m, tmp_sem[i]);
            float s = 0.f;
            #pragma unroll
            for (int i = 0; i < CS; i++) { e_sem[i] = __expf(tmp_sem[i] - m); s += e_sem[i]; }
            float is = 1.0f / s;
            #pragma unroll
            for (int i = 0; i < CS; i++) e_sem[i] *= is;
        }

        float sem_new[CS];
        #pragma unroll
        for (int o2 = 0; o2 < CS; o2++) {
            float acc = tmp_sem[o2];
            #pragma unroll
            for (int j = 0; j < CI; j++) acc = fmaf(s_mis[j * CS + o2], e_ins[j], acc);
            sem_new[o2] = acc;
        }
        float ins_new[CI];
        #pragma unroll
        for (int j = 0; j < CI; j++) {
            float acc = tmp_ins[j];
            #pragma unroll
            for (int s2 = 0; s2 < CS; s2++) acc = fmaf(s_csi[j * CS + s2], e_sem[s2], acc);
            ins_new[j] = acc;
        }

        float qs[CS], qi[CI];
        {
            float m = -1e30f;
            #pragma unroll
            for (int i = 0; i < CS; i++) m = fmaxf(m, sem_new[i]);
            float s = 0.f;
            #pragma unroll
            for (int i = 0; i < CS; i++) { qs[i] = __expf(sem_new[i] - m); s += qs[i]; }
            float is = 1.0f / s;
            #pragma unroll
            for (int i = 0; i < CS; i++) qs[i] *= is;
        }
        {
            float m = -1e30f;
            #pragma unroll
            for (int j = 0; j < CI; j++) m = fmaxf(m, ins_new[j]);
            float s = 0.f;
            #pragma unroll
            for (int j = 0; j < CI; j++) { qi[j] = __expf(ins_new[j] - m); s += qi[j]; }
            float is = 1.0f / s;
            #pragma unroll
            for (int j = 0; j < CI; j++) qi[j] *= is;
        }

        if (dout) {
            #pragma unroll
            for (int i = 0; i < CS; i++) dout[i * HW + p] = qs[i];
            #pragma unroll
            for (int j = 0; j < CI; j++) dout[(CS + j) * HW + p] = qi[j];
        } else {
            #pragma unroll
            for (int cp = 0; cp < CS / 2; cp++)
                qn2[cp * HW + p] = __floats2half2_rn(qs[2 * cp], qs[2 * cp + 1]);
            #pragma unroll
            for (int cp = 0; cp < CI / 2; cp++)
                qn2[(CS / 2 + cp) * HW + p] = __floats2half2_rn(qi[2 * cp], qi[2 * cp + 1]);
        }
    }
}

// ---------------- launch ----------------
extern "C" void kernel_launch(void* const* d_in, const int* in_sizes, int n_in,
                              void* d_out, int out_size)
{
    const float* img    = (const float*)d_in[0];
    const float* slog   = (const float*)d_in[1];
    const float* ilog   = (const float*)d_in[2];
    const int*   labels = (const int*)  d_in[3];
    const float* ssw    = (const float*)d_in[4];
    const float* sbw    = (const float*)d_in[5];
    const float* compat = (const float*)d_in[6];
    const float* isw    = (const float*)d_in[7];
    const float* ibw    = (const float*)d_in[8];
    const float* cis    = (const float*)d_in[9];
    const float* csi    = (const float*)d_in[10];
    float* out = (float*)d_out;

    const int FUSED_SMEM = (CP * TSZ + 144 + 192 + 192 + 16 + 16 + 12 + 12) * 4;
    cudaFuncSetAttribute(kFused, cudaFuncAttributeMaxDynamicSharedMemorySize, FUSED_SMEM);

    dim3 grdInit(W_ / 64, H_ / 4);            // 10 x 120
    dim3 grdBlur(W_ / BTX, H_ / BTY, CP);     // 10 x 15 x 14
    dim3 grdFused(W_ / FTX, H_ / FTY);        // 10 x 60

    kInit<<<grdInit, 256>>>(img, slog, ilog);

    // iter 0: q in A, write B
    kBlur<<<grdBlur, 256>>>(0);
    kFused<<<grdFused, 256, FUSED_SMEM>>>(0, nullptr, labels, ssw, sbw, compat, isw, ibw, cis, csi);
    // iter 1: q in B, write A
    kBlur<<<grdBlur, 256>>>(1);
    kFused<<<grdFused, 256, FUSED_SMEM>>>(1, nullptr, labels, ssw, sbw, compat, isw, ibw, cis, csi);
    // iter 2: q in A, write final output
    kBlur<<<grdBlur, 256>>>(0);
    kFused<<<grdFused, 256, FUSED_SMEM>>>(0, out, labels, ssw, sbw, compat, isw, ibw, cis, csi);
}

// round 15
// speedup vs baseline: 3.3341x; 3.3341x over previous
#include <cuda_runtime.h>
#include <cuda_fp16.h>

#define W_  640
#define H_  480
#define HW  307200
#define CS  12
#define CI  16
#define CT  28
#define CP  14    // channel pairs (sem pairs 0..5, ins pairs 6..13)

// ex2.approx.f16x2: one MUFU op, two exps (base 2)
__device__ __forceinline__ __half2 h2ex2(__half2 a) {
    __half2 d;
    asm("ex2.approx.f16x2 %0, %1;"
        : "=r"(*(unsigned*)&d) : "r"(*(unsigned*)&a));
    return d;
}

// ---------------- scratch (device globals, no allocation) ----------------
// Weight pair planes: o2=0..11 hold offsets (2*o2 + (o2>=6), +1); plane 12 = center (.x)
__device__ __half2 g_w2[13 * HW];
__device__ __half2 g_qa[CP * HW];    // q buffer A, channel-pair packed
__device__ __half2 g_qb[CP * HW];    // q buffer B
__device__ __half2 g_blur2[CP * HW]; // blur output, channel-pair packed

// 13-tap Gaussian sigma=3 as fp16x2 bit patterns (k,k)
__constant__ unsigned c_gkh2[13] = {
    0x24BF24BFu, 0x28602860u, 0x2B362B36u, 0x2D522D52u, 0x2F062F06u,
    0x30263026u, 0x30623062u, 0x30263026u, 0x2F062F06u, 0x2D522D52u,
    0x2B362B36u, 0x28602860u, 0x24BF24BFu};

// -sd_o * (1/18) * log2(e), o = dy*5+dx
__constant__ float c_sdl[25] = {
    -0.6411978f, -0.4007486f, -0.3205989f, -0.4007486f, -0.6411978f,
    -0.4007486f, -0.1602994f, -0.0801497f, -0.1602994f, -0.4007486f,
    -0.3205989f, -0.0801497f,  0.0f,       -0.0801497f, -0.3205989f,
    -0.4007486f, -0.1602994f, -0.0801497f, -0.1602994f, -0.4007486f,
    -0.6411978f, -0.4007486f, -0.3205989f, -0.4007486f, -0.6411978f};

#define KC   (-32.0598869f)             // -(1/(2*0.15^2)) * log2(e)
#define L2E  (1.4426950408889634f)

// select weight for raw offset o (0..24) from the pair-packed register array
__device__ __forceinline__ __half wsel(const __half2* w, int o) {
    if (o < 12)  return (o & 1) ? __high2half(w[o >> 1]) : __low2half(w[o >> 1]);
    if (o == 12) return __low2half(w[12]);
    return ((o - 1) & 1) ? __high2half(w[(o - 1) >> 1]) : __low2half(w[(o - 1) >> 1]);
}

// ---------------- init: bilateral weights + initial softmax ----------------
__global__ void __launch_bounds__(256) kInit(const float* __restrict__ img,
                                             const float* __restrict__ slog,
                                             const float* __restrict__ ilog)
{
    __shared__ float simg[3][8][68];

    int tid = threadIdx.x;
    int x0 = blockIdx.x * 64;
    int y0 = blockIdx.y * 4;

    for (int idx = tid; idx < 8 * 68; idx += 256) {
        int r  = idx / 68;
        int cc = idx - r * 68;
        int gy = min(max(y0 + r - 2, 0), H_ - 1);
        int gx = min(max(x0 + cc - 2, 0), W_ - 1);
        int gp = gy * W_ + gx;
        simg[0][r][cc] = __ldg(img + gp);
        simg[1][r][cc] = __ldg(img + HW + gp);
        simg[2][r][cc] = __ldg(img + 2 * HW + gp);
    }
    __syncthreads();

    int tx = tid & 63, ty = tid >> 6;
    int p  = (y0 + ty) * W_ + x0 + tx;

    float r0 = simg[0][ty + 2][tx + 2];
    float g0 = simg[1][ty + 2][tx + 2];
    float b0 = simg[2][ty + 2][tx + 2];

    // 24 non-center weights as 12 f16x2 exps; center weight = 1 exactly
    float2 ef[12];
    float den = 1.0f;
    #pragma unroll
    for (int o2 = 0; o2 < 12; o2++) {
        int offA = 2 * o2 + (o2 >= 6 ? 1 : 0);
        int offB = offA + 1;
        float arg[2];
        #pragma unroll
        for (int k = 0; k < 2; k++) {
            int o  = k ? offB : offA;
            int dy = o / 5, dx = o % 5;
            float dr = r0 - simg[0][ty + dy][tx + dx];
            float dg = g0 - simg[1][ty + dy][tx + dx];
            float db = b0 - simg[2][ty + dy][tx + dx];
            float cd = fmaf(db, db, fmaf(dg, dg, dr * dr));
            arg[k] = fmaf(cd, KC, c_sdl[o]);
        }
        __half2 e2 = h2ex2(__floats2half2_rn(arg[0], arg[1]));
        float2 f = __half22float2(e2);
        den += f.x + f.y;
        ef[o2] = f;
    }
    float inv = __fdividef(1.0f, den);
    #pragma unroll
    for (int o2 = 0; o2 < 12; o2++)
        g_w2[o2 * HW + p] = __floats2half2_rn(ef[o2].x * inv, ef[o2].y * inv);
    g_w2[12 * HW + p] = __floats2half2_rn(inv, 0.f);

    // initial softmaxes via f16x2 ex2 (q stored fp16 anyway)
    {
        float t[CS];
        float m = -1e30f;
        #pragma unroll
        for (int c = 0; c < CS; c++) { t[c] = __ldg(slog + c * HW + p); m = fmaxf(m, t[c]); }
        float mL = m * L2E;
        float2 ef2[CS / 2];
        float s = 0.f;
        #pragma unroll
        for (int cp = 0; cp < CS / 2; cp++) {
            float a0 = fmaf(t[2 * cp],     L2E, -mL);
            float a1 = fmaf(t[2 * cp + 1], L2E, -mL);
            float2 f = __half22float2(h2ex2(__floats2half2_rn(a0, a1)));
            s += f.x + f.y;
            ef2[cp] = f;
        }
        float is = __fdividef(1.0f, s);
        #pragma unroll
        for (int cp = 0; cp < CS / 2; cp++)
            g_qa[cp * HW + p] = __floats2half2_rn(ef2[cp].x * is, ef2[cp].y * is);
    }
    {
        float t[CI];
        float m = -1e30f;
        #pragma unroll
        for (int c = 0; c < CI; c++) { t[c] = __ldg(ilog + c * HW + p); m = fmaxf(m, t[c]); }
        float mL = m * L2E;
        float2 ef2[CI / 2];
        float s = 0.f;
        #pragma unroll
        for (int cp = 0; cp < CI / 2; cp++) {
            float a0 = fmaf(t[2 * cp],     L2E, -mL);
            float a1 = fmaf(t[2 * cp + 1], L2E, -mL);
            float2 f = __half22float2(h2ex2(__floats2half2_rn(a0, a1)));
            s += f.x + f.y;
            ef2[cp] = f;
        }
        float is = __fdividef(1.0f, s);
        #pragma unroll
        for (int cp = 0; cp < CI / 2; cp++)
            g_qa[(CS / 2 + cp) * HW + p] = __floats2half2_rn(ef2[cp].x * is, ef2[cp].y * is);
    }
}

// ---------------- fused separable blur, all-fp16 HFMA2 path ------------------
#define BTX 64
#define BTY 32
#define HR  (BTY + 12)   // 44

__global__ void __launch_bounds__(256, 6) kBlur(int src)
{
    const __half2* q = src ? g_qb : g_qa;
    __shared__ __half2 sH[HR][BTX];

    int c  = blockIdx.z;                 // pair index
    int x0 = blockIdx.x * BTX;
    int y0 = blockIdx.y * BTY;
    const __half2* plane = q + c * HW;
    int tid = threadIdx.x;

    bool interior = (blockIdx.x >= 1 && blockIdx.x <= 8 &&
                     blockIdx.y >= 1 && blockIdx.y <= (H_ / BTY) - 2);

    // H stage: 44 rows x 8 groups of 8 outputs = 352 tasks
    for (int t = tid; t < HR * 8; t += 256) {
        int r = t >> 3;
        int g = t & 7;
        int gy = y0 + r - 6;
        int xb = x0 + g * 8 - 8;         // 4-elem (16B) aligned
        __half2 f16[24];
        if (interior) {
            #pragma unroll
            for (int s = 0; s < 6; s++) {
                float4 v = __ldg((const float4*)(plane + gy * W_ + xb) + s);
                *(float4*)&f16[s * 4] = v;
            }
        } else if (gy >= 0 && gy < H_) {
            const __half2* row = plane + gy * W_;
            #pragma unroll
            for (int s = 0; s < 6; s++) {
                int xs = xb + s * 4;
                if (xs >= 0 && xs + 3 < W_) {
                    float4 v = __ldg((const float4*)(row + xs));
                    *(float4*)&f16[s * 4] = v;
                } else {
                    #pragma unroll
                    for (int k = 0; k < 4; k++) {
                        int xx = xs + k;
                        f16[s * 4 + k] = (xx >= 0 && xx < W_) ? __ldg(row + xx)
                                                              : __float2half2_rn(0.f);
                    }
                }
            }
        } else {
            #pragma unroll
            for (int k = 0; k < 24; k++) f16[k] = __float2half2_rn(0.f);
        }
        #pragma unroll
        for (int j = 0; j < 8; j++) {
            __half2 a = __float2half2_rn(0.f);
            #pragma unroll
            for (int tt = 0; tt < 13; tt++)
                a = __hfma2(*(const __half2*)&c_gkh2[tt], f16[j + 2 + tt], a);
            sH[r][g * 8 + j] = a;
        }
    }
    __syncthreads();

    // V stage: each thread 8 consecutive rows, sliding window over 20 sH rows
    int tx = tid & 63, ty = tid >> 6;    // ty 0..3
    __half2 acc[8];
    #pragma unroll
    for (int k = 0; k < 8; k++) acc[k] = __float2half2_rn(0.f);
    #pragma unroll
    for (int t = 0; t < 20; t++) {
        __half2 v = sH[ty * 8 + t][tx];
        #pragma unroll
        for (int k = 0; k < 8; k++) {
            int tt = t - k;
            if (tt >= 0 && tt < 13)
                acc[k] = __hfma2(*(const __half2*)&c_gkh2[tt], v, acc[k]);
        }
    }
    #pragma unroll
    for (int k = 0; k < 8; k++)
        g_blur2[c * HW + (y0 + ty * 8 + k) * W_ + x0 + tx] = acc[k];
}

// ---------------- fused: bilateral (HFMA2, 2-row blocked) + compat + cross ---
#define FTX 64
#define FTY 8
#define TCOL 72
#define TROW 12
#define TSZ  (TCOL * TROW)   // 864 half2 per pair-plane

__global__ void __launch_bounds__(256, 2) kFused(
    int src, float* __restrict__ dout,
    const float* __restrict__ slog, const float* __restrict__ ilog,
    const int*   __restrict__ labels,
    const float* __restrict__ ssw_g, const float* __restrict__ sbw_g,
    const float* __restrict__ compat_g,
    const float* __restrict__ isw_g, const float* __restrict__ ibw_g,
    const float* __restrict__ cis_g, const float* __restrict__ csi_g)
{
    extern __shared__ float sm[];
    __half2* sqh     = (__half2*)sm;              // CP * TSZ half2
    float* s_compat  = sm + CP * TSZ;             // 144
    float* s_mis     = s_compat + 144;            // 192
    float* s_csi     = s_mis + 192;               // 192
    float* s_sw      = s_csi + 192;               // 16
    float* s_bw      = s_sw + 16;                 // 16
    float* s_ssw     = s_bw + 16;                 // 12
    float* s_sbw     = s_ssw + 12;                // 12

    const __half2* q = src ? g_qb : g_qa;
    __half2* qn2 = src ? g_qa : g_qb;

    int tid = threadIdx.x;

    if (tid < CS * CS) s_compat[tid] = compat_g[tid];
    if (tid >= 160 && tid < 160 + CI) {
        int j = tid - 160;
        int l = labels[j];
        s_sw[j] = isw_g[l];
        s_bw[j] = ibw_g[l];
        #pragma unroll
        for (int s = 0; s < CS; s++) {
            s_mis[j * CS + s] = cis_g[l * CS + s];
            s_csi[j * CS + s] = csi_g[l * CS + s];
        }
    }
    if (tid >= 192 && tid < 192 + CS) {
        int s = tid - 192;
        s_ssw[s] = ssw_g[s];
        s_sbw[s] = sbw_g[s];
    }

    int x0 = blockIdx.x * FTX;
    int y0 = blockIdx.y * FTY;

    // fill q tile (half2 pairs) for all 14 pair-planes
    if (blockIdx.x >= 1 && blockIdx.x <= 8) {
        // 12 rows x 18 float4 groups = 216 tasks
        if (tid < TROW * (TCOL / 4)) {
            int r  = tid / (TCOL / 4);
            int c4 = tid - r * (TCOL / 4);
            int gy = min(max(y0 + r - 2, 0), H_ - 1);
            #pragma unroll
            for (int cp = 0; cp < CP; cp++) {
                float4 v = __ldg((const float4*)(q + cp * HW + gy * W_ + x0 - 4) + c4);
                *(float4*)(sqh + cp * TSZ + r * TCOL + c4 * 4) = v;
            }
        }
    } else {
        for (int idx = tid; idx < TROW * TCOL; idx += 256) {
            int r  = idx / TCOL;
            int cc = idx - r * TCOL;
            int gy = min(max(y0 + r - 2, 0), H_ - 1);
            int gx = min(max(x0 + cc - 4, 0), W_ - 1);
            #pragma unroll
            for (int cp = 0; cp < CP; cp++)
                sqh[cp * TSZ + r * TCOL + cc] = __ldg(q + cp * HW + gy * W_ + gx);
        }
    }
    __syncthreads();

    int tx = tid & 63;
    int r0 = (tid >> 6) * 2;             // this thread's two output rows: r0, r0+1
    int p0 = (y0 + r0) * W_ + x0 + tx;
    int p1 = p0 + W_;

    // per-pixel weights for both rows
    __half2 wph0[13], wph1[13];
    #pragma unroll
    for (int o2 = 0; o2 < 13; o2++) {
        wph0[o2] = __ldg(&g_w2[o2 * HW + p0]);
        wph1[o2] = __ldg(&g_w2[o2 * HW + p1]);
    }

    // ---- bilateral: shared 6x5 window serves both rows; 420 LDS, 700 HFMA2 --
    __half2 acc0[CP], acc1[CP];
    #pragma unroll
    for (int cp = 0; cp < CP; cp++) {
        acc0[cp] = __float2half2_rn(0.f);
        acc1[cp] = __float2half2_rn(0.f);
    }

    #pragma unroll
    for (int k = 0; k < 6; k++) {
        #pragma unroll
        for (int dx = 0; dx < 5; dx++) {
            const __half2* base = sqh + (r0 + k) * TCOL + (tx + dx + 2);
            __half2 w0b = __float2half2_rn(0.f), w1b = __float2half2_rn(0.f);
            if (k < 5)  w0b = __half2half2(wsel(wph0, k * 5 + dx));
            if (k >= 1) w1b = __half2half2(wsel(wph1, (k - 1) * 5 + dx));
            #pragma unroll
            for (int cp = 0; cp < CP; cp++) {
                __half2 v = base[cp * TSZ];
                if (k < 5)  acc0[cp] = __hfma2(w0b, v, acc0[cp]);
                if (k >= 1) acc1[cp] = __hfma2(w1b, v, acc1[cp]);
            }
        }
    }

    // ---- per-pixel epilogue, fully unrolled over the two rows ----
    #pragma unroll
    for (int px = 0; px < 2; px++) {
        int p = px ? p1 : p0;

        float bil[CT];
        #pragma unroll
        for (int cp = 0; cp < CP; cp++) {
            float2 f = __half22float2(px ? acc1[cp] : acc0[cp]);
            bil[2 * cp]     = f.x;
            bil[2 * cp + 1] = f.y;
        }

        float blv[CT];
        #pragma unroll
        for (int cp = 0; cp < CP; cp++) {
            float2 b = __half22float2(__ldg(&g_blur2[cp * HW + p]));
            blv[2 * cp]     = b.x;
            blv[2 * cp + 1] = b.y;
        }

        float contrib[CS];
        #pragma unroll
        for (int s = 0; s < CS; s++)
            contrib[s] = s_ssw[s] * blv[s] + s_sbw[s] * bil[s];

        float tmp_sem[CS];
        #pragma unroll
        for (int o2 = 0; o2 < CS; o2++) {
            float acc = __ldg(slog + o2 * HW + p);
            #pragma unroll
            for (int i = 0; i < CS; i++) acc = fmaf(s_compat[i * CS + o2], contrib[i], acc);
            tmp_sem[o2] = acc;
        }

        float tmp_ins[CI];
        #pragma unroll
        for (int j = 0; j < CI; j++)
            tmp_ins[j] = __ldg(ilog + j * HW + p) + s_sw[j] * blv[CS + j] + s_bw[j] * bil[CS + j];

        float e_ins[CI];
        {
            float m = -1e30f;
            #pragma unroll
            for (int j = 0; j < CI; j++) m = fmaxf(m, tmp_ins[j]);
            float s = 0.f;
            #pragma unroll
            for (int j = 0; j < CI; j++) { e_ins[j] = __expf(tmp_ins[j] - m); s += e_ins[j]; }
            float is = 1.0f / s;
            #pragma unroll
            for (int j = 0; j < CI; j++) e_ins[j] *= is;
        }
        float e_sem[CS];
        {
            float m = -1e30f;
            #pragma unroll
            for (int i = 0; i < CS; i++) m = fmaxf(m, tmp_sem[i]);
            float s = 0.f;
            #pragma unroll
            for (int i = 0; i < CS; i++) { e_sem[i] = __expf(tmp_sem[i] - m); s += e_sem[i]; }
            float is = 1.0f / s;
            #pragma unroll
            for (int i = 0; i < CS; i++) e_sem[i] *= is;
        }

        float sem_new[CS];
        #pragma unroll
        for (int o2 = 0; o2 < CS; o2++) {
            float acc = tmp_sem[o2];
            #pragma unroll
            for (int j = 0; j < CI; j++) acc = fmaf(s_mis[j * CS + o2], e_ins[j], acc);
            sem_new[o2] = acc;
        }
        float ins_new[CI];
        #pragma unroll
        for (int j = 0; j < CI; j++) {
            float acc = tmp_ins[j];
            #pragma unroll
            for (int s2 = 0; s2 < CS; s2++) acc = fmaf(s_csi[j * CS + s2], e_sem[s2], acc);
            ins_new[j] = acc;
        }

        float qs[CS], qi[CI];
        {
            float m = -1e30f;
            #pragma unroll
            for (int i = 0; i < CS; i++) m = fmaxf(m, sem_new[i]);
            float s = 0.f;
            #pragma unroll
            for (int i = 0; i < CS; i++) { qs[i] = __expf(sem_new[i] - m); s += qs[i]; }
            float is = 1.0f / s;
            #pragma unroll
            for (int i = 0; i < CS; i++) qs[i] *= is;
        }
        {
            float m = -1e30f;
            #pragma unroll
            for (int j = 0; j < CI; j++) m = fmaxf(m, ins_new[j]);
            float s = 0.f;
            #pragma unroll
            for (int j = 0; j < CI; j++) { qi[j] = __expf(ins_new[j] - m); s += qi[j]; }
            float is = 1.0f / s;
            #pragma unroll
            for (int j = 0; j < CI; j++) qi[j] *= is;
        }

        if (dout) {
            #pragma unroll
            for (int i = 0; i < CS; i++) dout[i * HW + p] = qs[i];
            #pragma unroll
            for (int j = 0; j < CI; j++) dout[(CS + j) * HW + p] = qi[j];
        } else {
            #pragma unroll
            for (int cp = 0; cp < CS / 2; cp++)
                qn2[cp * HW + p] = __floats2half2_rn(qs[2 * cp], qs[2 * cp + 1]);
            #pragma unroll
            for (int cp = 0; cp < CI / 2; cp++)
                qn2[(CS / 2 + cp) * HW + p] = __floats2half2_rn(qi[2 * cp], qi[2 * cp + 1]);
        }
    }
}

// ---------------- launch ----------------
extern "C" void kernel_launch(void* const* d_in, const int* in_sizes, int n_in,
                              void* d_out, int out_size)
{
    const float* img    = (const float*)d_in[0];
    const float* slog   = (const float*)d_in[1];
    const float* ilog   = (const float*)d_in[2];
    const int*   labels = (const int*)  d_in[3];
    const float* ssw    = (const float*)d_in[4];
    const float* sbw    = (const float*)d_in[5];
    const float* compat = (const float*)d_in[6];
    const float* isw    = (const float*)d_in[7];
    const float* ibw    = (const float*)d_in[8];
    const float* cis    = (const float*)d_in[9];
    const float* csi    = (const float*)d_in[10];
    float* out = (float*)d_out;

    const int FUSED_SMEM = (CP * TSZ + 144 + 192 + 192 + 16 + 16 + 12 + 12) * 4;
    cudaFuncSetAttribute(kFused, cudaFuncAttributeMaxDynamicSharedMemorySize, FUSED_SMEM);

    dim3 grdInit(W_ / 64, H_ / 4);            // 10 x 120
    dim3 grdBlur(W_ / BTX, H_ / BTY, CP);     // 10 x 15 x 14
    dim3 grdFused(W_ / FTX, H_ / FTY);        // 10 x 60

    kInit<<<grdInit, 256>>>(img, slog, ilog);

    // iter 0: q in A, write B
    kBlur<<<grdBlur, 256>>>(0);
    kFused<<<grdFused, 256, FUSED_SMEM>>>(0, nullptr, slog, ilog, labels, ssw, sbw, compat, isw, ibw, cis, csi);
    // iter 1: q in B, write A
    kBlur<<<grdBlur, 256>>>(1);
    kFused<<<grdFused, 256, FUSED_SMEM>>>(1, nullptr, slog, ilog, labels, ssw, sbw, compat, isw, ibw, cis, csi);
    // iter 2: q in A, write final output
    kBlur<<<grdBlur, 256>>>(0);
    kFused<<<grdFused, 256, FUSED_SMEM>>>(0, out, slog, ilog, labels, ssw, sbw, compat, isw, ibw, cis, csi);
}

// round 16
// speedup vs baseline: 3.4349x; 1.0303x over previous
#include <cuda_runtime.h>
#include <cuda_fp16.h>

#define W_  640
#define H_  480
#define HW  307200
#define CS  12
#define CI  16
#define CT  28
#define CP  14    // channel pairs (sem pairs 0..5, ins pairs 6..13)

// ex2.approx.f16x2: one MUFU op, two exps (base 2)
__device__ __forceinline__ __half2 h2ex2(__half2 a) {
    __half2 d;
    asm("ex2.approx.f16x2 %0, %1;"
        : "=r"(*(unsigned*)&d) : "r"(*(unsigned*)&a));
    return d;
}

// ---------------- scratch (device globals, no allocation) ----------------
// Weight pair planes: o2=0..11 hold offsets (2*o2 + (o2>=6), +1); plane 12 = center (.x)
__device__ __half2 g_w2[13 * HW];
__device__ __half2 g_qa[CP * HW];    // q buffer A, channel-pair packed
__device__ __half2 g_qb[CP * HW];    // q buffer B
__device__ __half2 g_blur2[CP * HW]; // blur output, channel-pair packed

// 13-tap Gaussian sigma=3 as fp16x2 bit patterns (k,k)
__constant__ unsigned c_gkh2[13] = {
    0x24BF24BFu, 0x28602860u, 0x2B362B36u, 0x2D522D52u, 0x2F062F06u,
    0x30263026u, 0x30623062u, 0x30263026u, 0x2F062F06u, 0x2D522D52u,
    0x2B362B36u, 0x28602860u, 0x24BF24BFu};

// -sd_o * (1/18) * log2(e), o = dy*5+dx
__constant__ float c_sdl[25] = {
    -0.6411978f, -0.4007486f, -0.3205989f, -0.4007486f, -0.6411978f,
    -0.4007486f, -0.1602994f, -0.0801497f, -0.1602994f, -0.4007486f,
    -0.3205989f, -0.0801497f,  0.0f,       -0.0801497f, -0.3205989f,
    -0.4007486f, -0.1602994f, -0.0801497f, -0.1602994f, -0.4007486f,
    -0.6411978f, -0.4007486f, -0.3205989f, -0.4007486f, -0.6411978f};

#define KC   (-32.0598869f)             // -(1/(2*0.15^2)) * log2(e)
#define L2E  (1.4426950408889634f)

// select weight for raw offset o (0..24) from the pair-packed register array
__device__ __forceinline__ __half wsel(const __half2* w, int o) {
    if (o < 12)  return (o & 1) ? __high2half(w[o >> 1]) : __low2half(w[o >> 1]);
    if (o == 12) return __low2half(w[12]);
    return ((o - 1) & 1) ? __high2half(w[(o - 1) >> 1]) : __low2half(w[(o - 1) >> 1]);
}

// ---------------- init: bilateral weights + initial softmax ----------------
__global__ void __launch_bounds__(256) kInit(const float* __restrict__ img,
                                             const float* __restrict__ slog,
                                             const float* __restrict__ ilog)
{
    __shared__ float simg[3][8][68];

    int tid = threadIdx.x;
    int x0 = blockIdx.x * 64;
    int y0 = blockIdx.y * 4;

    for (int idx = tid; idx < 8 * 68; idx += 256) {
        int r  = idx / 68;
        int cc = idx - r * 68;
        int gy = min(max(y0 + r - 2, 0), H_ - 1);
        int gx = min(max(x0 + cc - 2, 0), W_ - 1);
        int gp = gy * W_ + gx;
        simg[0][r][cc] = __ldg(img + gp);
        simg[1][r][cc] = __ldg(img + HW + gp);
        simg[2][r][cc] = __ldg(img + 2 * HW + gp);
    }
    __syncthreads();

    int tx = tid & 63, ty = tid >> 6;
    int p  = (y0 + ty) * W_ + x0 + tx;

    float r0 = simg[0][ty + 2][tx + 2];
    float g0 = simg[1][ty + 2][tx + 2];
    float b0 = simg[2][ty + 2][tx + 2];

    // 24 non-center weights as 12 f16x2 exps; center weight = 1 exactly
    float2 ef[12];
    float den = 1.0f;
    #pragma unroll
    for (int o2 = 0; o2 < 12; o2++) {
        int offA = 2 * o2 + (o2 >= 6 ? 1 : 0);
        int offB = offA + 1;
        float arg[2];
        #pragma unroll
        for (int k = 0; k < 2; k++) {
            int o  = k ? offB : offA;
            int dy = o / 5, dx = o % 5;
            float dr = r0 - simg[0][ty + dy][tx + dx];
            float dg = g0 - simg[1][ty + dy][tx + dx];
            float db = b0 - simg[2][ty + dy][tx + dx];
            float cd = fmaf(db, db, fmaf(dg, dg, dr * dr));
            arg[k] = fmaf(cd, KC, c_sdl[o]);
        }
        __half2 e2 = h2ex2(__floats2half2_rn(arg[0], arg[1]));
        float2 f = __half22float2(e2);
        den += f.x + f.y;
        ef[o2] = f;
    }
    float inv = __fdividef(1.0f, den);
    #pragma unroll
    for (int o2 = 0; o2 < 12; o2++)
        g_w2[o2 * HW + p] = __floats2half2_rn(ef[o2].x * inv, ef[o2].y * inv);
    g_w2[12 * HW + p] = __floats2half2_rn(inv, 0.f);

    // initial softmaxes via f16x2 ex2 (q stored fp16 anyway)
    {
        float t[CS];
        float m = -1e30f;
        #pragma unroll
        for (int c = 0; c < CS; c++) { t[c] = __ldg(slog + c * HW + p); m = fmaxf(m, t[c]); }
        float mL = m * L2E;
        float2 ef2[CS / 2];
        float s = 0.f;
        #pragma unroll
        for (int cp = 0; cp < CS / 2; cp++) {
            float a0 = fmaf(t[2 * cp],     L2E, -mL);
            float a1 = fmaf(t[2 * cp + 1], L2E, -mL);
            float2 f = __half22float2(h2ex2(__floats2half2_rn(a0, a1)));
            s += f.x + f.y;
            ef2[cp] = f;
        }
        float is = __fdividef(1.0f, s);
        #pragma unroll
        for (int cp = 0; cp < CS / 2; cp++)
            g_qa[cp * HW + p] = __floats2half2_rn(ef2[cp].x * is, ef2[cp].y * is);
    }
    {
        float t[CI];
        float m = -1e30f;
        #pragma unroll
        for (int c = 0; c < CI; c++) { t[c] = __ldg(ilog + c * HW + p); m = fmaxf(m, t[c]); }
        float mL = m * L2E;
        float2 ef2[CI / 2];
        float s = 0.f;
        #pragma unroll
        for (int cp = 0; cp < CI / 2; cp++) {
            float a0 = fmaf(t[2 * cp],     L2E, -mL);
            float a1 = fmaf(t[2 * cp + 1], L2E, -mL);
            float2 f = __half22float2(h2ex2(__floats2half2_rn(a0, a1)));
            s += f.x + f.y;
            ef2[cp] = f;
        }
        float is = __fdividef(1.0f, s);
        #pragma unroll
        for (int cp = 0; cp < CI / 2; cp++)
            g_qa[(CS / 2 + cp) * HW + p] = __floats2half2_rn(ef2[cp].x * is, ef2[cp].y * is);
    }
}

// ---------------- fused separable blur, all-fp16 HFMA2 path ------------------
#define BTX 64
#define BTY 48
#define HR  (BTY + 12)   // 60

__global__ void __launch_bounds__(256) kBlur(int src)
{
    const __half2* q = src ? g_qb : g_qa;
    __shared__ __half2 sH[HR][BTX];

    int c  = blockIdx.z;                 // pair index
    int x0 = blockIdx.x * BTX;
    int y0 = blockIdx.y * BTY;
    const __half2* plane = q + c * HW;
    int tid = threadIdx.x;

    bool interior = (blockIdx.x >= 1 && blockIdx.x <= 8 &&
                     blockIdx.y >= 1 && blockIdx.y <= (H_ / BTY) - 2);

    // H stage: 60 rows x 8 groups of 8 outputs = 480 tasks
    for (int t = tid; t < HR * 8; t += 256) {
        int r = t >> 3;
        int g = t & 7;
        int gy = y0 + r - 6;
        int xb = x0 + g * 8 - 8;         // 4-elem (16B) aligned
        __half2 f16[24];
        if (interior) {
            #pragma unroll
            for (int s = 0; s < 6; s++) {
                float4 v = __ldg((const float4*)(plane + gy * W_ + xb) + s);
                *(float4*)&f16[s * 4] = v;
            }
        } else if (gy >= 0 && gy < H_) {
            const __half2* row = plane + gy * W_;
            #pragma unroll
            for (int s = 0; s < 6; s++) {
                int xs = xb + s * 4;
                if (xs >= 0 && xs + 3 < W_) {
                    float4 v = __ldg((const float4*)(row + xs));
                    *(float4*)&f16[s * 4] = v;
                } else {
                    #pragma unroll
                    for (int k = 0; k < 4; k++) {
                        int xx = xs + k;
                        f16[s * 4 + k] = (xx >= 0 && xx < W_) ? __ldg(row + xx)
                                                              : __float2half2_rn(0.f);
                    }
                }
            }
        } else {
            #pragma unroll
            for (int k = 0; k < 24; k++) f16[k] = __float2half2_rn(0.f);
        }
        #pragma unroll
        for (int j = 0; j < 8; j++) {
            __half2 a = __float2half2_rn(0.f);
            #pragma unroll
            for (int tt = 0; tt < 13; tt++)
                a = __hfma2(*(const __half2*)&c_gkh2[tt], f16[j + 2 + tt], a);
            sH[r][g * 8 + j] = a;
        }
    }
    __syncthreads();

    // V stage: each thread 12 consecutive rows, sliding window over 24 sH rows
    int tx = tid & 63, ty = tid >> 6;    // ty 0..3
    __half2 acc[12];
    #pragma unroll
    for (int k = 0; k < 12; k++) acc[k] = __float2half2_rn(0.f);
    #pragma unroll
    for (int t = 0; t < 24; t++) {
        __half2 v = sH[ty * 12 + t][tx];
        #pragma unroll
        for (int k = 0; k < 12; k++) {
            int tt = t - k;
            if (tt >= 0 && tt < 13)
                acc[k] = __hfma2(*(const __half2*)&c_gkh2[tt], v, acc[k]);
        }
    }
    #pragma unroll
    for (int k = 0; k < 12; k++)
        g_blur2[c * HW + (y0 + ty * 12 + k) * W_ + x0 + tx] = acc[k];
}

// ---------------- fused: bilateral (HFMA2, 2-row blocked) + compat + cross ---
#define FTX 64
#define FTY 8
#define TCOL 72
#define TROW 12
#define TSZ  (TCOL * TROW)   // 864 half2 per pair-plane

__global__ void __launch_bounds__(256, 2) kFused(
    int src, float* __restrict__ dout,
    const float* __restrict__ slog, const float* __restrict__ ilog,
    const int*   __restrict__ labels,
    const float* __restrict__ ssw_g, const float* __restrict__ sbw_g,
    const float* __restrict__ compat_g,
    const float* __restrict__ isw_g, const float* __restrict__ ibw_g,
    const float* __restrict__ cis_g, const float* __restrict__ csi_g)
{
    extern __shared__ float sm[];
    __half2* sqh     = (__half2*)sm;              // CP * TSZ half2
    float* s_compat  = sm + CP * TSZ;             // 144
    float* s_mis     = s_compat + 144;            // 192
    float* s_csi     = s_mis + 192;               // 192
    float* s_sw      = s_csi + 192;               // 16
    float* s_bw      = s_sw + 16;                 // 16
    float* s_ssw     = s_bw + 16;                 // 12
    float* s_sbw     = s_ssw + 12;                // 12

    const __half2* q = src ? g_qb : g_qa;
    __half2* qn2 = src ? g_qa : g_qb;

    int tid = threadIdx.x;

    if (tid < CS * CS) s_compat[tid] = compat_g[tid];
    if (tid >= 160 && tid < 160 + CI) {
        int j = tid - 160;
        int l = labels[j];
        s_sw[j] = isw_g[l];
        s_bw[j] = ibw_g[l];
        #pragma unroll
        for (int s = 0; s < CS; s++) {
            s_mis[j * CS + s] = cis_g[l * CS + s];
            s_csi[j * CS + s] = csi_g[l * CS + s];
        }
    }
    if (tid >= 192 && tid < 192 + CS) {
        int s = tid - 192;
        s_ssw[s] = ssw_g[s];
        s_sbw[s] = sbw_g[s];
    }

    int x0 = blockIdx.x * FTX;
    int y0 = blockIdx.y * FTY;

    // fill q tile (half2 pairs) for all 14 pair-planes
    if (blockIdx.x >= 1 && blockIdx.x <= 8) {
        // 12 rows x 18 float4 groups = 216 tasks
        if (tid < TROW * (TCOL / 4)) {
            int r  = tid / (TCOL / 4);
            int c4 = tid - r * (TCOL / 4);
            int gy = min(max(y0 + r - 2, 0), H_ - 1);
            #pragma unroll
            for (int cp = 0; cp < CP; cp++) {
                float4 v = __ldg((const float4*)(q + cp * HW + gy * W_ + x0 - 4) + c4);
                *(float4*)(sqh + cp * TSZ + r * TCOL + c4 * 4) = v;
            }
        }
    } else {
        for (int idx = tid; idx < TROW * TCOL; idx += 256) {
            int r  = idx / TCOL;
            int cc = idx - r * TCOL;
            int gy = min(max(y0 + r - 2, 0), H_ - 1);
            int gx = min(max(x0 + cc - 4, 0), W_ - 1);
            #pragma unroll
            for (int cp = 0; cp < CP; cp++)
                sqh[cp * TSZ + r * TCOL + cc] = __ldg(q + cp * HW + gy * W_ + gx);
        }
    }
    __syncthreads();

    int tx = tid & 63;
    int r0 = (tid >> 6) * 2;             // this thread's two output rows: r0, r0+1
    int p0 = (y0 + r0) * W_ + x0 + tx;
    int p1 = p0 + W_;

    // per-pixel weights for both rows
    __half2 wph0[13], wph1[13];
    #pragma unroll
    for (int o2 = 0; o2 < 13; o2++) {
        wph0[o2] = __ldg(&g_w2[o2 * HW + p0]);
        wph1[o2] = __ldg(&g_w2[o2 * HW + p1]);
    }

    // ---- bilateral: shared 6x5 window serves both rows; 420 LDS, 700 HFMA2 --
    __half2 acc0[CP], acc1[CP];
    #pragma unroll
    for (int cp = 0; cp < CP; cp++) {
        acc0[cp] = __float2half2_rn(0.f);
        acc1[cp] = __float2half2_rn(0.f);
    }

    #pragma unroll
    for (int k = 0; k < 6; k++) {
        #pragma unroll
        for (int dx = 0; dx < 5; dx++) {
            const __half2* base = sqh + (r0 + k) * TCOL + (tx + dx + 2);
            __half2 w0b = __float2half2_rn(0.f), w1b = __float2half2_rn(0.f);
            if (k < 5)  w0b = __half2half2(wsel(wph0, k * 5 + dx));
            if (k >= 1) w1b = __half2half2(wsel(wph1, (k - 1) * 5 + dx));
            #pragma unroll
            for (int cp = 0; cp < CP; cp++) {
                __half2 v = base[cp * TSZ];
                if (k < 5)  acc0[cp] = __hfma2(w0b, v, acc0[cp]);
                if (k >= 1) acc1[cp] = __hfma2(w1b, v, acc1[cp]);
            }
        }
    }

    // ---- per-pixel epilogue, fully unrolled over the two rows ----
    #pragma unroll
    for (int px = 0; px < 2; px++) {
        int p = px ? p1 : p0;

        float bil[CT];
        #pragma unroll
        for (int cp = 0; cp < CP; cp++) {
            float2 f = __half22float2(px ? acc1[cp] : acc0[cp]);
            bil[2 * cp]     = f.x;
            bil[2 * cp + 1] = f.y;
        }

        float blv[CT];
        #pragma unroll
        for (int cp = 0; cp < CP; cp++) {
            float2 b = __half22float2(__ldg(&g_blur2[cp * HW + p]));
            blv[2 * cp]     = b.x;
            blv[2 * cp + 1] = b.y;
        }

        float contrib[CS];
        #pragma unroll
        for (int s = 0; s < CS; s++)
            contrib[s] = s_ssw[s] * blv[s] + s_sbw[s] * bil[s];

        float tmp_sem[CS];
        #pragma unroll
        for (int o2 = 0; o2 < CS; o2++) {
            float acc = __ldg(slog + o2 * HW + p);
            #pragma unroll
            for (int i = 0; i < CS; i++) acc = fmaf(s_compat[i * CS + o2], contrib[i], acc);
            tmp_sem[o2] = acc;
        }

        float tmp_ins[CI];
        #pragma unroll
        for (int j = 0; j < CI; j++)
            tmp_ins[j] = __ldg(ilog + j * HW + p) + s_sw[j] * blv[CS + j] + s_bw[j] * bil[CS + j];

        float e_ins[CI];
        {
            float m = -1e30f;
            #pragma unroll
            for (int j = 0; j < CI; j++) m = fmaxf(m, tmp_ins[j]);
            float s = 0.f;
            #pragma unroll
            for (int j = 0; j < CI; j++) { e_ins[j] = __expf(tmp_ins[j] - m); s += e_ins[j]; }
            float is = 1.0f / s;
            #pragma unroll
            for (int j = 0; j < CI; j++) e_ins[j] *= is;
        }
        float e_sem[CS];
        {
            float m = -1e30f;
            #pragma unroll
            for (int i = 0; i < CS; i++) m = fmaxf(m, tmp_sem[i]);
            float s = 0.f;
            #pragma unroll
            for (int i = 0; i < CS; i++) { e_sem[i] = __expf(tmp_sem[i] - m); s += e_sem[i]; }
            float is = 1.0f / s;
            #pragma unroll
            for (int i = 0; i < CS; i++) e_sem[i] *= is;
        }

        float sem_new[CS];
        #pragma unroll
        for (int o2 = 0; o2 < CS; o2++) {
            float acc = tmp_sem[o2];
            #pragma unroll
            for (int j = 0; j < CI; j++) acc = fmaf(s_mis[j * CS + o2], e_ins[j], acc);
            sem_new[o2] = acc;
        }
        float ins_new[CI];
        #pragma unroll
        for (int j = 0; j < CI; j++) {
            float acc = tmp_ins[j];
            #pragma unroll
            for (int s2 = 0; s2 < CS; s2++) acc = fmaf(s_csi[j * CS + s2], e_sem[s2], acc);
            ins_new[j] = acc;
        }

        float qs[CS], qi[CI];
        {
            float m = -1e30f;
            #pragma unroll
            for (int i = 0; i < CS; i++) m = fmaxf(m, sem_new[i]);
            float s = 0.f;
            #pragma unroll
            for (int i = 0; i < CS; i++) { qs[i] = __expf(sem_new[i] - m); s += qs[i]; }
            float is = 1.0f / s;
            #pragma unroll
            for (int i = 0; i < CS; i++) qs[i] *= is;
        }
        {
            float m = -1e30f;
            #pragma unroll
            for (int j = 0; j < CI; j++) m = fmaxf(m, ins_new[j]);
            float s = 0.f;
            #pragma unroll
            for (int j = 0; j < CI; j++) { qi[j] = __expf(ins_new[j] - m); s += qi[j]; }
            float is = 1.0f / s;
            #pragma unroll
            for (int j = 0; j < CI; j++) qi[j] *= is;
        }

        if (dout) {
            #pragma unroll
            for (int i = 0; i < CS; i++) dout[i * HW + p] = qs[i];
            #pragma unroll
            for (int j = 0; j < CI; j++) dout[(CS + j) * HW + p] = qi[j];
        } else {
            #pragma unroll
            for (int cp = 0; cp < CS / 2; cp++)
                qn2[cp * HW + p] = __floats2half2_rn(qs[2 * cp], qs[2 * cp + 1]);
            #pragma unroll
            for (int cp = 0; cp < CI / 2; cp++)
                qn2[(CS / 2 + cp) * HW + p] = __floats2half2_rn(qi[2 * cp], qi[2 * cp + 1]);
        }
    }
}

// ---------------- launch ----------------
extern "C" void kernel_launch(void* const* d_in, const int* in_sizes, int n_in,
                              void* d_out, int out_size)
{
    const float* img    = (const float*)d_in[0];
    const float* slog   = (const float*)d_in[1];
    const float* ilog   = (const float*)d_in[2];
    const int*   labels = (const int*)  d_in[3];
    const float* ssw    = (const float*)d_in[4];
    const float* sbw    = (const float*)d_in[5];
    const float* compat = (const float*)d_in[6];
    const float* isw    = (const float*)d_in[7];
    const float* ibw    = (const float*)d_in[8];
    const float* cis    = (const float*)d_in[9];
    const float* csi    = (const float*)d_in[10];
    float* out = (float*)d_out;

    const int FUSED_SMEM = (CP * TSZ + 144 + 192 + 192 + 16 + 16 + 12 + 12) * 4;
    cudaFuncSetAttribute(kFused, cudaFuncAttributeMaxDynamicSharedMemorySize, FUSED_SMEM);

    dim3 grdInit(W_ / 64, H_ / 4);            // 10 x 120
    dim3 grdBlur(W_ / BTX, H_ / BTY, CP);     // 10 x 10 x 14
    dim3 grdFused(W_ / FTX, H_ / FTY);        // 10 x 60

    kInit<<<grdInit, 256>>>(img, slog, ilog);

    // iter 0: q in A, write B
    kBlur<<<grdBlur, 256>>>(0);
    kFused<<<grdFused, 256, FUSED_SMEM>>>(0, nullptr, slog, ilog, labels, ssw, sbw, compat, isw, ibw, cis, csi);
    // iter 1: q in B, write A
    kBlur<<<grdBlur, 256>>>(1);
    kFused<<<grdFused, 256, FUSED_SMEM>>>(1, nullptr, slog, ilog, labels, ssw, sbw, compat, isw, ibw, cis, csi);
    // iter 2: q in A, write final output
    kBlur<<<grdBlur, 256>>>(0);
    kFused<<<grdFused, 256, FUSED_SMEM>>>(0, out, slog, ilog, labels, ssw, sbw, compat, isw, ibw, cis, csi);
}